// round 4
// baseline (speedup 1.0000x reference)
#include <cuda_runtime.h>
#include <cuda_bf16.h>

#define TT    128
#define HORZ  24
#define NTH   64
#define LOG2E 1.44269504f

typedef unsigned long long u64;

// ---------------- device helpers ----------------
__device__ __forceinline__ void fma2(u64 &acc, u64 w, u64 h){
    asm("fma.rn.f32x2 %0, %1, %2, %0;" : "+l"(acc) : "l"(w), "l"(h));
}
__device__ __forceinline__ float hsum2(u64 a){
    return __uint_as_float((unsigned)a) + __uint_as_float((unsigned)(a >> 32));
}
__device__ __forceinline__ float ex2f(float x){ float y; asm("ex2.approx.f32 %0, %1;" : "=f"(y) : "f"(x)); return y; }
__device__ __forceinline__ float rcpf(float x){ float y; asm("rcp.approx.f32 %0, %1;" : "=f"(y) : "f"(x)); return y; }
__device__ __forceinline__ float sigm(float x){ return rcpf(1.0f + ex2f(-LOG2E * x)); }
__device__ __forceinline__ float tanh_acc(float x){
    float xx = fminf(15.0f, fmaxf(-15.0f, x));
    float e  = ex2f(2.0f * LOG2E * xx);
    return (e - 1.0f) * rcpf(e + 1.0f);
}
__device__ __forceinline__ float tanh_fast(float x){
    float y; asm("tanh.approx.f32 %0, %1;" : "=f"(y) : "f"(x)); return y;
}

// ---------------- smem layout (float offsets) ----------------
#define SM_H      0                       // 129 x 64
#define SM_HP     (SM_H + 129*64)         // 128 x 33
#define SM_XS     (SM_HP + 128*33)        // 128
#define SM_DBUF   (SM_XS + 128)           // 2 x 64
#define SM_DPPART (SM_DBUF + 128)         // 64
#define SM_DPV    (SM_DPPART + 64)        // 32
#define SM_EBUF   (SM_DPV + 32)           // 128
#define SM_VD     (SM_EBUF + 128)         // 32
#define SM_RED    (SM_VD + 32)            // 8
#define SM_BUFR   (SM_RED + 8)            // 64
#define SM_BUFZ   (SM_BUFR + 64)          // 64
#define SM_BUFN   (SM_BUFZ + 64)          // 64
#define SM_BUFHP  (SM_BUFN + 64)          // 32
#define SM_CP     (SM_BUFHP + 32)         // 128
#define SM_FLOATS (SM_CP + 128)
#define SMEM_BYTES (SM_FLOATS * 4)

extern "C" __global__ void __launch_bounds__(NTH, 4)
darnn_kernel(const float* __restrict__ x,
             const float* __restrict__ W_ih_e, const float* __restrict__ W_hh_e,
             const float* __restrict__ b_ih_e, const float* __restrict__ b_hh_e,
             const float* __restrict__ W_init, const float* __restrict__ b_init,
             const float* __restrict__ W_ih_d, const float* __restrict__ W_hh_d,
             const float* __restrict__ b_ih_d, const float* __restrict__ b_hh_d,
             const float* __restrict__ W_d,    const float* __restrict__ U_d,
             const float* __restrict__ v_d,
             const float* __restrict__ W_out,  const float* __restrict__ b_out,
             const float* __restrict__ y0,
             float* __restrict__ out)
{
    extern __shared__ __align__(16) float sm[];
    float* H      = sm + SM_H;
    float* Hp     = sm + SM_HP;
    float* xs     = sm + SM_XS;
    float* dbuf   = sm + SM_DBUF;
    float* dppart = sm + SM_DPPART;
    float* dpv    = sm + SM_DPV;
    float* ebuf   = sm + SM_EBUF;
    float* vd     = sm + SM_VD;
    float* red    = sm + SM_RED;
    float* bufR   = sm + SM_BUFR;
    float* bufZ   = sm + SM_BUFZ;
    float* bufN   = sm + SM_BUFN;
    float* bufHp  = sm + SM_BUFHP;
    float* cp     = sm + SM_CP;

    const int j    = threadIdx.x;
    const int b    = blockIdx.x;
    const int lane = j & 31;
    const int w    = j >> 5;
    const int oj   = w * 32 + lane;          // output this thread finalizes
    const int od   = (1 - w) * 32 + lane;    // output it donates partials for

    // ---- encoder weights: 6 half-rows (outputs {lane, lane+32} x 3 gates, k-half = warp)
    u64 wra[16], wrb[16], wza[16], wzb[16], wna[16], wnb[16];
    {
        const u64* Ra = (const u64*)(W_hh_e + (lane)       * 64 + w * 32);
        const u64* Rb = (const u64*)(W_hh_e + (lane + 32)  * 64 + w * 32);
        const u64* Za = (const u64*)(W_hh_e + (64  + lane) * 64 + w * 32);
        const u64* Zb = (const u64*)(W_hh_e + (96  + lane) * 64 + w * 32);
        const u64* Na = (const u64*)(W_hh_e + (128 + lane) * 64 + w * 32);
        const u64* Nb = (const u64*)(W_hh_e + (160 + lane) * 64 + w * 32);
        #pragma unroll
        for (int k = 0; k < 16; k++){
            wra[k] = Ra[k]; wrb[k] = Rb[k];
            wza[k] = Za[k]; wzb[k] = Zb[k];
            wna[k] = Na[k]; wnb[k] = Nb[k];
        }
    }
    // H_proj weights: a = lane, k-half = warp
    u64 ud[16];
    {
        const u64* U = (const u64*)(U_d + lane * 64 + w * 32);
        #pragma unroll
        for (int k = 0; k < 16; k++) ud[k] = U[k];
    }
    float wih_r = W_ih_e[oj], wih_z = W_ih_e[64 + oj], wih_n = W_ih_e[128 + oj];
    float br  = b_ih_e[oj]       + b_hh_e[oj];
    float bz  = b_ih_e[64 + oj]  + b_hh_e[64 + oj];
    float bin = b_ih_e[128 + oj];
    float bhn = b_hh_e[128 + oj];

    xs[j]      = x[b * TT + j];
    xs[64 + j] = x[b * TT + 64 + j];
    H[j] = 0.0f;
    if (j < 32) vd[j] = v_d[j];
    __syncthreads();

    // ---------------- encoder: 128 GRU steps, k-split + fused H_proj ----------
    float hcur = 0.0f;
    for (int t = 0; t < TT; t++){
        const float* hrow = H + t * 64 + w * 32;   // this warp's k-half of h_{t-1}
        u64 ara = 0ULL, arb = 0ULL, aza = 0ULL, azb = 0ULL, ana = 0ULL, anb = 0ULL, ahp = 0ULL;
        #pragma unroll
        for (int k = 0; k < 8; k++){
            ulonglong2 h2 = *(const ulonglong2*)(hrow + k * 4);  // LDS.128 broadcast (half)
            fma2(ara, wra[2*k], h2.x); fma2(ara, wra[2*k+1], h2.y);
            fma2(arb, wrb[2*k], h2.x); fma2(arb, wrb[2*k+1], h2.y);
            fma2(aza, wza[2*k], h2.x); fma2(aza, wza[2*k+1], h2.y);
            fma2(azb, wzb[2*k], h2.x); fma2(azb, wzb[2*k+1], h2.y);
            fma2(ana, wna[2*k], h2.x); fma2(ana, wna[2*k+1], h2.y);
            fma2(anb, wnb[2*k], h2.x); fma2(anb, wnb[2*k+1], h2.y);
            fma2(ahp, ud[2*k],  h2.x); fma2(ahp, ud[2*k+1],  h2.y);
        }
        float pra = hsum2(ara), prb = hsum2(arb);
        float pza = hsum2(aza), pzb = hsum2(azb);
        float pna = hsum2(ana), pnb = hsum2(anb);
        float hpp = hsum2(ahp);
        // donate partials for output od, keep partials for oj
        float myR = w ? prb : pra, dnR = w ? pra : prb;
        float myZ = w ? pzb : pza, dnZ = w ? pza : pzb;
        float myN = w ? pnb : pna, dnN = w ? pna : pnb;
        bufR[od] = dnR; bufZ[od] = dnZ; bufN[od] = dnN;
        if (w == 0 && t) bufHp[lane] = hpp;
        __syncthreads();                              // B1: partials visible
        if (w == 1 && t) Hp[(t - 1) * 33 + lane] = hpp + bufHp[lane];
        float xt = xs[t];
        float r  = sigm(fmaf(xt, wih_r, br) + myR + bufR[oj]);
        float z  = sigm(fmaf(xt, wih_z, bz) + myZ + bufZ[oj]);
        float n  = tanh_acc(fmaf(xt, wih_n, bin) + r * (myN + bufN[oj] + bhn));
        hcur = n + z * (hcur - n);
        H[(t + 1) * 64 + oj] = hcur;
        __syncthreads();                              // B2: h_new visible
    }

    // ---- H_proj tail: row 127 from h_127 (H row 128) ----
    {
        const float* hrow = H + TT * 64 + w * 32;
        u64 ahp = 0ULL;
        #pragma unroll
        for (int k = 0; k < 8; k++){
            ulonglong2 h2 = *(const ulonglong2*)(hrow + k * 4);
            fma2(ahp, ud[2*k], h2.x); fma2(ahp, ud[2*k+1], h2.y);
        }
        float hpp = hsum2(ahp);
        if (w == 0) bufHp[lane] = hpp;
        __syncthreads();
        if (w == 1) Hp[127 * 33 + lane] = hpp + bufHp[lane];
    }

    // ---------------- decoder init: d0 = W_init . h_T + b_init ----------------
    float dj;
    {
        const u64* Wi = (const u64*)(W_init + oj * 64);
        const float* hT = H + TT * 64;
        u64 acc = 0ULL;
        #pragma unroll
        for (int k = 0; k < 16; k++){
            ulonglong2 h2 = *(const ulonglong2*)(hT + k * 4);
            fma2(acc, Wi[2*k], h2.x); fma2(acc, Wi[2*k+1], h2.y);
        }
        dj = hsum2(acc) + b_init[oj];
        dbuf[oj] = dj;
    }

    // ---- reload weight regs with decoder GRU half-rows
    {
        const u64* Ra = (const u64*)(W_hh_d + (lane)       * 64 + w * 32);
        const u64* Rb = (const u64*)(W_hh_d + (lane + 32)  * 64 + w * 32);
        const u64* Za = (const u64*)(W_hh_d + (64  + lane) * 64 + w * 32);
        const u64* Zb = (const u64*)(W_hh_d + (96  + lane) * 64 + w * 32);
        const u64* Na = (const u64*)(W_hh_d + (128 + lane) * 64 + w * 32);
        const u64* Nb = (const u64*)(W_hh_d + (160 + lane) * 64 + w * 32);
        #pragma unroll
        for (int k = 0; k < 16; k++){
            wra[k] = Ra[k]; wrb[k] = Rb[k];
            wza[k] = Za[k]; wzb[k] = Zb[k];
            wna[k] = Na[k]; wnb[k] = Nb[k];
        }
    }
    wih_r = W_ih_d[oj]; wih_z = W_ih_d[64 + oj]; wih_n = W_ih_d[128 + oj];
    br  = b_ih_d[oj]      + b_hh_d[oj];
    bz  = b_ih_d[64 + oj] + b_hh_d[64 + oj];
    bin = b_ih_d[128 + oj];
    bhn = b_hh_d[128 + oj];
    const float wout_d = W_out[oj], wout_c = W_out[64 + oj];
    const float bo = b_out[0];
    float xdec = y0[0];
    __syncthreads();

    // ---------------- decoder: 24 steps ----------------
    for (int s = 0; s < HORZ; s++){
        const float* drow   = dbuf + (s & 1) * 64 + w * 32;
        float*       drow_n = dbuf + ((s + 1) & 1) * 64;

        // GRU on d, k-split
        u64 ara = 0ULL, arb = 0ULL, aza = 0ULL, azb = 0ULL, ana = 0ULL, anb = 0ULL;
        #pragma unroll
        for (int k = 0; k < 8; k++){
            ulonglong2 h2 = *(const ulonglong2*)(drow + k * 4);
            fma2(ara, wra[2*k], h2.x); fma2(ara, wra[2*k+1], h2.y);
            fma2(arb, wrb[2*k], h2.x); fma2(arb, wrb[2*k+1], h2.y);
            fma2(aza, wza[2*k], h2.x); fma2(aza, wza[2*k+1], h2.y);
            fma2(azb, wzb[2*k], h2.x); fma2(azb, wzb[2*k+1], h2.y);
            fma2(ana, wna[2*k], h2.x); fma2(ana, wna[2*k+1], h2.y);
            fma2(anb, wnb[2*k], h2.x); fma2(anb, wnb[2*k+1], h2.y);
        }
        {
            float pra = hsum2(ara), prb = hsum2(arb);
            float pza = hsum2(aza), pzb = hsum2(azb);
            float pna = hsum2(ana), pnb = hsum2(anb);
            float myR = w ? prb : pra, dnR = w ? pra : prb;
            float myZ = w ? pzb : pza, dnZ = w ? pza : pzb;
            float myN = w ? pnb : pna, dnN = w ? pna : pnb;
            bufR[od] = dnR; bufZ[od] = dnZ; bufN[od] = dnN;
            __syncthreads();                           // B1
            float r  = sigm(fmaf(xdec, wih_r, br) + myR + bufR[oj]);
            float z  = sigm(fmaf(xdec, wih_z, bz) + myZ + bufZ[oj]);
            float n  = tanh_acc(fmaf(xdec, wih_n, bin) + r * (myN + bufN[oj] + bhn));
            dj = n + z * (dj - n);
            drow_n[oj] = dj;
        }
        __syncthreads();                               // B2: d_new visible

        // d_proj split-k: a = lane, k-half = warp (W_d rows L1-resident)
        {
            const u64* Wd = (const u64*)(W_d + lane * 64 + w * 32);
            const float* dsrc = drow_n + w * 32;
            u64 acc = 0ULL;
            #pragma unroll
            for (int k = 0; k < 8; k++){
                ulonglong2 d2 = *(const ulonglong2*)(dsrc + k * 4);
                fma2(acc, Wd[2*k], d2.x); fma2(acc, Wd[2*k+1], d2.y);
            }
            dppart[j] = hsum2(acc);
        }
        __syncthreads();                               // B3
        if (j < 32) dpv[j] = dppart[j] + dppart[32 + j];
        __syncthreads();                               // B4

        // scores: warp w owns t in [64w, 64w+64): t1 = 64w+lane, t2 = t1+32
        const int t1 = 64 * w + lane, t2 = t1 + 32;
        float s1 = 0.0f, s2 = 0.0f;
        {
            const float* hp1 = Hp + t1 * 33;
            const float* hp2 = Hp + t2 * 33;
            #pragma unroll 8
            for (int a = 0; a < 32; a++){
                float dpa = dpv[a];
                float va  = vd[a];
                s1 = fmaf(va, tanh_fast(dpa + hp1[a]), s1);
                s2 = fmaf(va, tanh_fast(dpa + hp2[a]), s2);
            }
        }

        // softmax over 128 scores
        float m = fmaxf(s1, s2);
        #pragma unroll
        for (int o = 16; o > 0; o >>= 1) m = fmaxf(m, __shfl_xor_sync(0xffffffffu, m, o));
        if (lane == 0) red[w] = m;
        __syncthreads();                               // B5
        m = fmaxf(red[0], red[1]);
        float e1 = ex2f((s1 - m) * LOG2E);
        float e2 = ex2f((s2 - m) * LOG2E);
        ebuf[t1] = e1; ebuf[t2] = e2;
        float esum = e1 + e2;
        #pragma unroll
        for (int o = 16; o > 0; o >>= 1) esum += __shfl_xor_sync(0xffffffffu, esum, o);
        if (lane == 0) red[2 + w] = esum;
        __syncthreads();                               // B6: ebuf + sums ready
        float inv = rcpf(red[2] + red[3]);

        // ctx partials: warp w sums over its own t-range for all 64 j
        float c0 = 0.0f, c1 = 0.0f;
        {
            const float* Hbase = H + (64 * w + 1) * 64;
            const float* eb    = ebuf + 64 * w;
            #pragma unroll 8
            for (int tt = 0; tt < 64; tt++){
                float e = eb[tt];
                c0 = fmaf(e, Hbase[tt * 64 + lane],      c0);
                c1 = fmaf(e, Hbase[tt * 64 + lane + 32], c1);
            }
        }
        cp[w * 64 + lane]      = c0;
        cp[w * 64 + 32 + lane] = c1;
        __syncthreads();                               // B7
        float ctxj = (cp[oj] + cp[64 + oj]) * inv;

        // out scalar
        float part = fmaf(wout_d, dj, wout_c * ctxj);
        #pragma unroll
        for (int o = 16; o > 0; o >>= 1) part += __shfl_xor_sync(0xffffffffu, part, o);
        if (lane == 0) red[4 + w] = part;
        __syncthreads();                               // B8
        float val = red[4] + red[5] + bo;              // all threads compute
        if (j == 0) out[b * HORZ + s] = val;
        xdec = val;                                    // next decoder input (register)
    }
}

extern "C" void kernel_launch(void* const* d_in, const int* in_sizes, int n_in,
                              void* d_out, int out_size)
{
    (void)in_sizes; (void)n_in; (void)out_size;
    const float* x      = (const float*)d_in[0];
    const float* W_ih_e = (const float*)d_in[1];
    const float* W_hh_e = (const float*)d_in[2];
    const float* b_ih_e = (const float*)d_in[3];
    const float* b_hh_e = (const float*)d_in[4];
    // d_in[5..8] dead (input attention == identity)
    const float* W_init = (const float*)d_in[9];
    const float* b_init = (const float*)d_in[10];
    const float* W_ih_d = (const float*)d_in[11];
    const float* W_hh_d = (const float*)d_in[12];
    const float* b_ih_d = (const float*)d_in[13];
    const float* b_hh_d = (const float*)d_in[14];
    const float* W_d    = (const float*)d_in[15];
    const float* U_d    = (const float*)d_in[16];
    const float* v_d    = (const float*)d_in[17];
    const float* W_out  = (const float*)d_in[18];
    const float* b_out  = (const float*)d_in[19];
    const float* y0     = (const float*)d_in[20];
    float* out = (float*)d_out;

    cudaFuncSetAttribute(darnn_kernel, cudaFuncAttributeMaxDynamicSharedMemorySize, SMEM_BYTES);
    darnn_kernel<<<4096, NTH, SMEM_BYTES>>>(
        x, W_ih_e, W_hh_e, b_ih_e, b_hh_e,
        W_init, b_init, W_ih_d, W_hh_d, b_ih_d, b_hh_d,
        W_d, U_d, v_d, W_out, b_out, y0, out);
}

// round 6
// speedup vs baseline: 1.0579x; 1.0579x over previous
#include <cuda_runtime.h>
#include <cuda_bf16.h>

#define TT    128
#define HORZ  24
#define NTH   128
#define LOG2E 1.44269504f

typedef unsigned long long u64;

// ---------------- device helpers ----------------
__device__ __forceinline__ void fma2(u64 &acc, u64 w, u64 h){
    asm("fma.rn.f32x2 %0, %1, %2, %0;" : "+l"(acc) : "l"(w), "l"(h));
}
__device__ __forceinline__ float hsum2(u64 a){
    return __uint_as_float((unsigned)a) + __uint_as_float((unsigned)(a >> 32));
}
__device__ __forceinline__ float ex2f(float x){ float y; asm("ex2.approx.f32 %0, %1;" : "=f"(y) : "f"(x)); return y; }
__device__ __forceinline__ float rcpf(float x){ float y; asm("rcp.approx.f32 %0, %1;" : "=f"(y) : "f"(x)); return y; }
__device__ __forceinline__ float sigm(float x){ return rcpf(1.0f + ex2f(-LOG2E * x)); }
__device__ __forceinline__ float tanh_acc(float x){
    float xx = fminf(15.0f, fmaxf(-15.0f, x));
    float e  = ex2f(2.0f * LOG2E * xx);
    return (e - 1.0f) * rcpf(e + 1.0f);
}
__device__ __forceinline__ float tanh_fast(float x){
    float y; asm("tanh.approx.f32 %0, %1;" : "=f"(y) : "f"(x)); return y;
}

// ---------------- smem layout (float offsets) ----------------
#define SM_H      0                       // 129 x 64 (row 0 = h_{-1} = 0)
#define SM_HP     (SM_H + 129*64)         // 128 x 33 (stride-33 -> CF reads)
#define SM_XS     (SM_HP + 128*33)        // 128
#define SM_DBUF   (SM_XS + 128)           // 2 x 64 decoder hidden
#define SM_PR     (SM_DBUF + 128)         // 128 gate-r partials [kh][j]
#define SM_PZ     (SM_PR + 128)           // 128
#define SM_PN     (SM_PZ + 128)           // 128
#define SM_DPV    (SM_PN + 128)           // 32  d_proj
#define SM_EBUF   (SM_DPV + 32)           // 128 softmax numerators
#define SM_VD     (SM_EBUF + 128)         // 32  v_d
#define SM_RED    (SM_VD + 32)            // 16  cross-warp scratch
#define SM_CP     (SM_RED + 16)           // 128 ctx / d_proj partials
#define SM_FLOATS (SM_CP + 128)
#define SMEM_BYTES (SM_FLOATS * 4)        // 53.8 KB -> 4 CTAs/SM

extern "C" __global__ void __launch_bounds__(NTH, 4)
darnn_kernel(const float* __restrict__ x,
             const float* __restrict__ W_ih_e, const float* __restrict__ W_hh_e,
             const float* __restrict__ b_ih_e, const float* __restrict__ b_hh_e,
             const float* __restrict__ W_init, const float* __restrict__ b_init,
             const float* __restrict__ W_ih_d, const float* __restrict__ W_hh_d,
             const float* __restrict__ b_ih_d, const float* __restrict__ b_hh_d,
             const float* __restrict__ W_d,    const float* __restrict__ U_d,
             const float* __restrict__ v_d,
             const float* __restrict__ W_out,  const float* __restrict__ b_out,
             const float* __restrict__ y0,
             float* __restrict__ out)
{
    extern __shared__ __align__(16) float sm[];
    float* H    = sm + SM_H;
    float* Hp   = sm + SM_HP;
    float* xs   = sm + SM_XS;
    float* dbuf = sm + SM_DBUF;
    float* pR   = sm + SM_PR;
    float* pZ   = sm + SM_PZ;
    float* pN   = sm + SM_PN;
    float* dpv  = sm + SM_DPV;
    float* ebuf = sm + SM_EBUF;
    float* vd   = sm + SM_VD;
    float* red  = sm + SM_RED;
    float* cp   = sm + SM_CP;

    const int tid  = threadIdx.x;
    const int b    = blockIdx.x;
    const int lane = tid & 31;
    const int warp = tid >> 5;          // 0..3
    const int j    = ((warp >> 1) << 5) + lane;   // output unit 0..63
    const int kh   = warp & 1;          // k-half this thread accumulates
    const bool fin = (kh == 0);         // finalizing threads (warps 0, 2)

    // ---- encoder GRU weights: 3 half-rows (outputs j / 64+j / 128+j, k in [32kh,32kh+32))
    u64 wr[16], wz[16], wn[16];
    {
        const u64* Wr = (const u64*)(W_hh_e + (j)       * 64 + kh * 32);
        const u64* Wz = (const u64*)(W_hh_e + (64 + j)  * 64 + kh * 32);
        const u64* Wn = (const u64*)(W_hh_e + (128 + j) * 64 + kh * 32);
        #pragma unroll
        for (int k = 0; k < 16; k++){ wr[k] = Wr[k]; wz[k] = Wz[k]; wn[k] = Wn[k]; }
    }
    float wih_r = W_ih_e[j], wih_z = W_ih_e[64 + j], wih_n = W_ih_e[128 + j];
    float br  = b_ih_e[j]       + b_hh_e[j];
    float bz  = b_ih_e[64 + j]  + b_hh_e[64 + j];
    float bin = b_ih_e[128 + j];
    float bhn = b_hh_e[128 + j];

    xs[tid] = x[b * TT + tid];
    if (tid < 64) H[tid] = 0.0f;
    if (tid < 32) vd[tid] = v_d[tid];
    __syncthreads();

    // ---------------- encoder: 128 GRU steps, 4-warp k-split ----------------
    float hcur = 0.0f;
    for (int t = 0; t < TT; t++){
        const float* hrow = H + t * 64 + kh * 32;
        u64 ar = 0ULL, az = 0ULL, an = 0ULL;
        #pragma unroll
        for (int k = 0; k < 8; k++){
            ulonglong2 h2 = *(const ulonglong2*)(hrow + k * 4);  // LDS.128 broadcast
            fma2(ar, wr[2*k], h2.x); fma2(ar, wr[2*k+1], h2.y);
            fma2(az, wz[2*k], h2.x); fma2(az, wz[2*k+1], h2.y);
            fma2(an, wn[2*k], h2.x); fma2(an, wn[2*k+1], h2.y);
        }
        pR[kh * 64 + j] = hsum2(ar);
        pZ[kh * 64 + j] = hsum2(az);
        pN[kh * 64 + j] = hsum2(an);
        __syncthreads();                                   // B1: partials
        if (fin){
            float xt = xs[t];
            float r  = sigm(fmaf(xt, wih_r, br) + pR[j] + pR[64 + j]);
            float z  = sigm(fmaf(xt, wih_z, bz) + pZ[j] + pZ[64 + j]);
            float n  = tanh_acc(fmaf(xt, wih_n, bin) + r * (pN[j] + pN[64 + j] + bhn));
            hcur = n + z * (hcur - n);
            H[(t + 1) * 64 + j] = hcur;
        }
        __syncthreads();                                   // B2: h_new
    }

    // ---------------- H_proj pass: warp owns 32 t's, lane = a ----------------
    {
        u64 ud[32];
        const u64* U = (const u64*)(U_d + lane * 64);
        #pragma unroll
        for (int k = 0; k < 32; k++) ud[k] = U[k];
        for (int tt = 0; tt < 32; tt++){
            int t = warp * 32 + tt;
            const float* hrow = H + (t + 1) * 64;
            u64 acc = 0ULL;
            #pragma unroll
            for (int k = 0; k < 16; k++){
                ulonglong2 h2 = *(const ulonglong2*)(hrow + k * 4);
                fma2(acc, ud[2*k], h2.x); fma2(acc, ud[2*k+1], h2.y);
            }
            Hp[t * 33 + lane] = hsum2(acc);
        }
    }

    // ---------------- decoder init: d0 = W_init . h_T + b_init (k-split) ----
    float dj = 0.0f;
    {
        const ulonglong2* Wi = (const ulonglong2*)(W_init + j * 64 + kh * 32);
        const float* hT = H + TT * 64 + kh * 32;
        u64 acc = 0ULL;
        #pragma unroll
        for (int k = 0; k < 8; k++){
            ulonglong2 h2 = *(const ulonglong2*)(hT + k * 4);
            ulonglong2 w2 = Wi[k];
            fma2(acc, w2.x, h2.x); fma2(acc, w2.y, h2.y);
        }
        pR[kh * 64 + j] = hsum2(acc);
    }
    __syncthreads();
    if (fin){
        dj = pR[j] + pR[64 + j] + b_init[j];
        dbuf[j] = dj;
    }

    // ---- reload weight regs with decoder GRU half-rows
    {
        const u64* Wr = (const u64*)(W_hh_d + (j)       * 64 + kh * 32);
        const u64* Wz = (const u64*)(W_hh_d + (64 + j)  * 64 + kh * 32);
        const u64* Wn = (const u64*)(W_hh_d + (128 + j) * 64 + kh * 32);
        #pragma unroll
        for (int k = 0; k < 16; k++){ wr[k] = Wr[k]; wz[k] = Wz[k]; wn[k] = Wn[k]; }
    }
    wih_r = W_ih_d[j]; wih_z = W_ih_d[64 + j]; wih_n = W_ih_d[128 + j];
    br  = b_ih_d[j]      + b_hh_d[j];
    bz  = b_ih_d[64 + j] + b_hh_d[64 + j];
    bin = b_ih_d[128 + j];
    bhn = b_hh_d[128 + j];
    const float wout_d = W_out[j], wout_c = W_out[64 + j];
    const float bo = b_out[0];
    float xdec = y0[0];
    __syncthreads();                                       // dbuf ready

    // ---------------- decoder: 24 steps ----------------
    for (int s = 0; s < HORZ; s++){
        const float* drow   = dbuf + (s & 1) * 64;
        float*       drow_n = dbuf + ((s + 1) & 1) * 64;

        // GRU on d, 4-warp k-split
        {
            const float* hrow = drow + kh * 32;
            u64 ar = 0ULL, az = 0ULL, an = 0ULL;
            #pragma unroll
            for (int k = 0; k < 8; k++){
                ulonglong2 h2 = *(const ulonglong2*)(hrow + k * 4);
                fma2(ar, wr[2*k], h2.x); fma2(ar, wr[2*k+1], h2.y);
                fma2(az, wz[2*k], h2.x); fma2(az, wz[2*k+1], h2.y);
                fma2(an, wn[2*k], h2.x); fma2(an, wn[2*k+1], h2.y);
            }
            pR[kh * 64 + j] = hsum2(ar);
            pZ[kh * 64 + j] = hsum2(az);
            pN[kh * 64 + j] = hsum2(an);
        }
        __syncthreads();                                   // B1
        if (fin){
            float r  = sigm(fmaf(xdec, wih_r, br) + pR[j] + pR[64 + j]);
            float z  = sigm(fmaf(xdec, wih_z, bz) + pZ[j] + pZ[64 + j]);
            float n  = tanh_acc(fmaf(xdec, wih_n, bin) + r * (pN[j] + pN[64 + j] + bhn));
            dj = n + z * (dj - n);
            drow_n[j] = dj;
        }
        __syncthreads();                                   // B2: d_new

        // d_proj quarter-split: a = lane, k-quarter = warp (W_d L1-resident)
        {
            const ulonglong2* Wd = (const ulonglong2*)(W_d + lane * 64 + warp * 16);
            const float* dsrc = drow_n + warp * 16;
            u64 acc = 0ULL;
            #pragma unroll
            for (int k = 0; k < 4; k++){
                ulonglong2 d2 = *(const ulonglong2*)(dsrc + k * 4);
                ulonglong2 w2 = Wd[k];
                fma2(acc, w2.x, d2.x); fma2(acc, w2.y, d2.y);
            }
            cp[warp * 32 + lane] = hsum2(acc);
        }
        __syncthreads();                                   // B3
        if (tid < 32) dpv[tid] = (cp[tid] + cp[32 + tid]) + (cp[64 + tid] + cp[96 + tid]);
        __syncthreads();                                   // B4

        // scores: one t per thread; softmax WITHOUT max (|s| <= ~3, exp safe)
        {
            const float* hpt = Hp + tid * 33;
            float sc = 0.0f;
            #pragma unroll 8
            for (int a = 0; a < 32; a++)
                sc = fmaf(vd[a], tanh_fast(dpv[a] + hpt[a]), sc);
            float e = ex2f(sc * LOG2E);
            ebuf[tid] = e;
            float esum = e;
            #pragma unroll
            for (int o = 16; o > 0; o >>= 1) esum += __shfl_xor_sync(0xffffffffu, esum, o);
            if (lane == 0) red[4 + warp] = esum;
        }
        __syncthreads();                                   // B5: ebuf + sums
        float inv = rcpf((red[4] + red[5]) + (red[6] + red[7]));

        // ctx partials: thread (jc = tid&63, th = tid>>6) sums its 64-t range
        {
            const int jc = tid & 63, th = tid >> 6;
            const float* Hb = H + (th * 64 + 1) * 64;
            const float* eb = ebuf + th * 64;
            float c = 0.0f;
            #pragma unroll 8
            for (int t2 = 0; t2 < 64; t2++)
                c = fmaf(eb[t2], Hb[t2 * 64 + jc], c);
            cp[tid] = c;
        }
        __syncthreads();                                   // B6
        if (fin){
            float ctxj = (cp[j] + cp[64 + j]) * inv;
            float part = fmaf(wout_d, dj, wout_c * ctxj);
            #pragma unroll
            for (int o = 16; o > 0; o >>= 1) part += __shfl_xor_sync(0xffffffffu, part, o);
            if (lane == 0) red[8 + (warp >> 1)] = part;
        }
        __syncthreads();                                   // B7
        float val = red[8] + red[9] + bo;                  // all threads
        if (tid == 0) out[b * HORZ + s] = val;
        xdec = val;
    }
}

extern "C" void kernel_launch(void* const* d_in, const int* in_sizes, int n_in,
                              void* d_out, int out_size)
{
    (void)in_sizes; (void)n_in; (void)out_size;
    const float* x      = (const float*)d_in[0];
    const float* W_ih_e = (const float*)d_in[1];
    const float* W_hh_e = (const float*)d_in[2];
    const float* b_ih_e = (const float*)d_in[3];
    const float* b_hh_e = (const float*)d_in[4];
    // d_in[5..8] dead (input attention == softmax over singleton axis)
    const float* W_init = (const float*)d_in[9];
    const float* b_init = (const float*)d_in[10];
    const float* W_ih_d = (const float*)d_in[11];
    const float* W_hh_d = (const float*)d_in[12];
    const float* b_ih_d = (const float*)d_in[13];
    const float* b_hh_d = (const float*)d_in[14];
    const float* W_d    = (const float*)d_in[15];
    const float* U_d    = (const float*)d_in[16];
    const float* v_d    = (const float*)d_in[17];
    const float* W_out  = (const float*)d_in[18];
    const float* b_out  = (const float*)d_in[19];
    const float* y0     = (const float*)d_in[20];
    float* out = (float*)d_out;

    cudaFuncSetAttribute(darnn_kernel, cudaFuncAttributeMaxDynamicSharedMemorySize, SMEM_BYTES);
    darnn_kernel<<<4096, NTH, SMEM_BYTES>>>(
        x, W_ih_e, W_hh_e, b_ih_e, b_hh_e,
        W_init, b_init, W_ih_d, W_hh_d, b_ih_d, b_hh_d,
        W_d, U_d, v_d, W_out, b_out, y0, out);
}